// round 3
// baseline (speedup 1.0000x reference)
#include <cuda_runtime.h>
#include <cuda_bf16.h>
#include <math.h>

// Problem constants
#define BB 2
#define TT 1024
#define LL 8
#define EE 1024
#define NHH 16
#define HDD 64
#define VV 32000
#define FFF 4096
#define MM (BB * TT)   // 2048 rows

// ---------------------------------------------------------------------------
// Device scratch (allocation-free: __device__ globals)
// ---------------------------------------------------------------------------
__device__ __align__(256) float g_x[MM * EE];
__device__ __align__(256) float g_h[MM * EE];
__device__ __align__(256) float g_q[MM * EE];
__device__ __align__(256) float g_k[MM * EE];
__device__ __align__(256) float g_v[MM * EE];
__device__ __align__(256) float g_o[MM * EE];
__device__ __align__(256) float g_ffn[MM * FFF];
__device__ __align__(256) float g_attn[(size_t)BB * NHH * TT * TT];  // 134 MB

// ---------------------------------------------------------------------------
// cp.async helpers (Ampere+ LDGSTS; supported on sm_103a)
// ---------------------------------------------------------------------------
__device__ __forceinline__ void cp_async16(void* smem, const void* gmem) {
    unsigned saddr = (unsigned)__cvta_generic_to_shared(smem);
    asm volatile("cp.async.cg.shared.global [%0], [%1], 16;\n" :: "r"(saddr), "l"(gmem));
}
__device__ __forceinline__ void cp_commit() { asm volatile("cp.async.commit_group;\n" ::); }
__device__ __forceinline__ void cp_wait0()  { asm volatile("cp.async.wait_group 0;\n" ::); }

// ---------------------------------------------------------------------------
// Embedding: x[b,t,:] = tok_emb[idx[b,t],:] + pos_emb[t,:]
// ---------------------------------------------------------------------------
__global__ void embed_kernel(const int* __restrict__ idx,
                             const float* __restrict__ tok_emb,
                             const float* __restrict__ pos_emb,
                             float* __restrict__ x)
{
    int gid = blockIdx.x * blockDim.x + threadIdx.x;   // over MM*EE
    int bt = gid >> 10;          // /EE
    int e  = gid & (EE - 1);
    int t  = bt & (TT - 1);
    int tok = idx[bt];
    x[gid] = tok_emb[(size_t)tok * EE + e] + pos_emb[t * EE + e];
}

// ---------------------------------------------------------------------------
// LayerNorm: one block (256 threads) per row of EE=1024
// ---------------------------------------------------------------------------
__global__ void ln_kernel(const float* __restrict__ x,
                          const float* __restrict__ scale,
                          const float* __restrict__ bias,
                          float* __restrict__ out)
{
    int row = blockIdx.x;
    int tid = threadIdx.x;
    const float* xr = x + (size_t)row * EE;
    float v[4];
#pragma unroll
    for (int i = 0; i < 4; i++) v[i] = xr[tid + i * 256];

    __shared__ float red[256];
    float s = v[0] + v[1] + v[2] + v[3];
    red[tid] = s;
    __syncthreads();
    for (int off = 128; off > 0; off >>= 1) {
        if (tid < off) red[tid] += red[tid + off];
        __syncthreads();
    }
    float mean = red[0] * (1.0f / EE);
    __syncthreads();

    float sq = 0.f;
#pragma unroll
    for (int i = 0; i < 4; i++) { float d = v[i] - mean; sq += d * d; }
    red[tid] = sq;
    __syncthreads();
    for (int off = 128; off > 0; off >>= 1) {
        if (tid < off) red[tid] += red[tid + off];
        __syncthreads();
    }
    float var = red[0] * (1.0f / EE);
    float rstd = rsqrtf(var + 1e-5f);

    float* orow = out + (size_t)row * EE;
#pragma unroll
    for (int i = 0; i < 4; i++) {
        int col = tid + i * 256;
        orow[col] = (v[i] - mean) * rstd * scale[col] + bias[col];
    }
}

// ---------------------------------------------------------------------------
// SGEMM: C[M,N] = A[M,K] @ W[K,N] (+bias) (+res) (GELU optional)
// BM=BN=128, BK=16, 256 threads, 8x8 per thread.
// Double-buffered cp.async pipeline: GMEM->SMEM copies for tile t+1 overlap
// the 1024-FMA compute block for tile t. One __syncthreads per K-tile pair.
// Requires M%128==0, N%128==0, K%16==0 (all satisfied here).
// ---------------------------------------------------------------------------
__device__ __forceinline__ float gelu_exact(float c) {
    return 0.5f * c * (1.0f + erff(c * 0.70710678118654752f));
}

#define BKK 16

template <bool ADD_RES, bool DO_GELU>
__global__ __launch_bounds__(256, 2)
void sgemm_kernel(const float* __restrict__ A, const float* __restrict__ W,
                  const float* __restrict__ bias, const float* __restrict__ res,
                  float* __restrict__ C, int Mdim, int Ndim, int Kdim)
{
    // As kept row-major [m][k] (+4 pad kills conflicts on strided column reads)
    __shared__ __align__(16) float As[2][128][BKK + 4];
    __shared__ __align__(16) float Bs[2][BKK][128];

    int tid = threadIdx.x;
    int bm = blockIdx.y * 128;
    int bn = blockIdx.x * 128;

    // A tile: 128 rows x 16 floats = 512 x 16B chunks; 2 chunks per thread
    int am0 = tid >> 1;                  // chunk c=tid    : m = c>>2... (use direct mapping below)
    // B tile: 16 rows x 128 floats = 512 x 16B chunks; 2 chunks per thread

    int ty = tid >> 4;                   // 16x16 thread grid for compute
    int tx = tid & 15;

    float acc[8][8];
#pragma unroll
    for (int i = 0; i < 8; i++)
#pragma unroll
        for (int j = 0; j < 8; j++) acc[i][j] = 0.f;

    int ntiles = Kdim / BKK;

    // --- copy issue helper (inlined twice) ---
    // A chunks: c in {tid, tid+256}: m = c>>2, j = c&3  -> As[buf][m][j*4]
    // B chunks: c in {tid, tid+256}: kk = c>>5, n4 = (c&31)*4 -> Bs[buf][kk][n4]
#define ISSUE_TILE(buf, k0)                                                          \
    {                                                                                \
        int c0 = tid, c1 = tid + 256;                                                \
        cp_async16(&As[buf][c0 >> 2][(c0 & 3) * 4],                                  \
                   A + (size_t)(bm + (c0 >> 2)) * Kdim + (k0) + (c0 & 3) * 4);       \
        cp_async16(&As[buf][c1 >> 2][(c1 & 3) * 4],                                  \
                   A + (size_t)(bm + (c1 >> 2)) * Kdim + (k0) + (c1 & 3) * 4);       \
        cp_async16(&Bs[buf][c0 >> 5][(c0 & 31) * 4],                                 \
                   W + (size_t)((k0) + (c0 >> 5)) * Ndim + bn + (c0 & 31) * 4);      \
        cp_async16(&Bs[buf][c1 >> 5][(c1 & 31) * 4],                                 \
                   W + (size_t)((k0) + (c1 >> 5)) * Ndim + bn + (c1 & 31) * 4);      \
        cp_commit();                                                                 \
    }

    ISSUE_TILE(0, 0);

    int buf = 0;
    for (int t = 0; t < ntiles; t++) {
        cp_wait0();
        __syncthreads();                 // tile t resident; prev compute finished

        if (t + 1 < ntiles) ISSUE_TILE(buf ^ 1, (t + 1) * BKK);

#pragma unroll
        for (int k = 0; k < BKK; k++) {
            float a[8], b[8];
#pragma unroll
            for (int i = 0; i < 8; i++) a[i] = As[buf][ty * 8 + i][k];
            float4 b0 = *(const float4*)&Bs[buf][k][tx * 8];
            float4 b1 = *(const float4*)&Bs[buf][k][tx * 8 + 4];
            b[0]=b0.x; b[1]=b0.y; b[2]=b0.z; b[3]=b0.w;
            b[4]=b1.x; b[5]=b1.y; b[6]=b1.z; b[7]=b1.w;
#pragma unroll
            for (int i = 0; i < 8; i++)
#pragma unroll
                for (int j = 0; j < 8; j++)
                    acc[i][j] = fmaf(a[i], b[j], acc[i][j]);
        }
        __syncthreads();                 // all reads of buf done before t+2 overwrites it
        buf ^= 1;
    }
#undef ISSUE_TILE

#pragma unroll
    for (int i = 0; i < 8; i++) {
        int row = bm + ty * 8 + i;
#pragma unroll
        for (int j = 0; j < 8; j++) {
            int col = bn + tx * 8 + j;
            float c = acc[i][j];
            if (bias) c += bias[col];
            if (ADD_RES) c += res[(size_t)row * Ndim + col];
            if (DO_GELU) c = gelu_exact(c);
            C[(size_t)row * Ndim + col] = c;
        }
    }
}

// ---------------------------------------------------------------------------
// Attention scores: attn[b,h,t,s] = (q[b,t,h,:] . k[b,s,h,:]) * 0.125
// 32x32 tiles, skip fully-causal-masked tiles. Softmax cleans up partial mask.
// ---------------------------------------------------------------------------
__global__ void scores_kernel(const float* __restrict__ q,
                              const float* __restrict__ k,
                              float* __restrict__ attn)
{
    int bh = blockIdx.z;
    int b = bh >> 4, h = bh & 15;
    int t0 = blockIdx.y * 32, s0 = blockIdx.x * 32;
    if (s0 > t0 + 31) return;   // fully masked tile

    __shared__ float Qs[32][64];
    __shared__ float Ks[32][65];   // pad -> conflict-free column reads
    int tid = threadIdx.x;
#pragma unroll
    for (int i = 0; i < 8; i++) {
        int e = tid + i * 256;
        int r = e >> 6, d = e & 63;
        Qs[r][d] = q[(size_t)(b * TT + t0 + r) * EE + h * 64 + d];
        Ks[r][d] = k[(size_t)(b * TT + s0 + r) * EE + h * 64 + d];
    }
    __syncthreads();

    int tx = tid & 31, ty = tid >> 5;
    float acc[4] = {0.f, 0.f, 0.f, 0.f};
#pragma unroll 16
    for (int d = 0; d < 64; d++) {
        float kv = Ks[tx][d];
        acc[0] = fmaf(Qs[ty][d],      kv, acc[0]);
        acc[1] = fmaf(Qs[ty +  8][d], kv, acc[1]);
        acc[2] = fmaf(Qs[ty + 16][d], kv, acc[2]);
        acc[3] = fmaf(Qs[ty + 24][d], kv, acc[3]);
    }
#pragma unroll
    for (int i = 0; i < 4; i++) {
        int t = t0 + ty + 8 * i;
        attn[((size_t)bh * TT + t) * TT + s0 + tx] = acc[i] * 0.125f;
    }
}

// ---------------------------------------------------------------------------
// Causal softmax over a row of length t+1; zero-fill s > t.
// ---------------------------------------------------------------------------
__global__ void softmax_kernel(float* __restrict__ attn)
{
    int r = blockIdx.x;             // (b*NH + h)*TT + t
    int t = r & (TT - 1);
    float* row = attn + (size_t)r * TT;
    int n = t + 1;
    int tid = threadIdx.x;
    __shared__ float red[128];

    float m = -1e30f;
    for (int i = tid; i < n; i += 128) m = fmaxf(m, row[i]);
    red[tid] = m;
    __syncthreads();
    for (int off = 64; off > 0; off >>= 1) {
        if (tid < off) red[tid] = fmaxf(red[tid], red[tid + off]);
        __syncthreads();
    }
    m = red[0];
    __syncthreads();

    float s = 0.f;
    for (int i = tid; i < n; i += 128) s += __expf(row[i] - m);
    red[tid] = s;
    __syncthreads();
    for (int off = 64; off > 0; off >>= 1) {
        if (tid < off) red[tid] += red[tid + off];
        __syncthreads();
    }
    float inv = 1.0f / red[0];

    for (int i = tid; i < TT; i += 128)
        row[i] = (i < n) ? __expf(row[i] - m) * inv : 0.f;
}

// ---------------------------------------------------------------------------
// PV: o[b,t,h,:] = sum_s attn[b,h,t,s] * v[b,s,h,:]
// 64 t-rows x 64 d-cols per block; break at causal frontier (attn zeros beyond).
// ---------------------------------------------------------------------------
__global__ void pv_kernel(const float* __restrict__ attn,
                          const float* __restrict__ v,
                          float* __restrict__ o)
{
    int bh = blockIdx.y;
    int b = bh >> 4, h = bh & 15;
    int t0 = blockIdx.x * 64;
    int tid = threadIdx.x;
    int d = tid & 63, rg = tid >> 6;   // 4 row-groups of 16

    __shared__ float As[64][17];
    __shared__ float Vs[16][64];
    float acc[16];
#pragma unroll
    for (int r = 0; r < 16; r++) acc[r] = 0.f;

    for (int s0 = 0; s0 < TT; s0 += 16) {
        if (s0 > t0 + 63) break;       // everything further is zero
#pragma unroll
        for (int i = 0; i < 4; i++) {
            int e = tid + i * 256;
            int r = e >> 4, c = e & 15;
            As[r][c] = attn[((size_t)bh * TT + t0 + r) * TT + s0 + c];
        }
#pragma unroll
        for (int i = 0; i < 4; i++) {
            int e = tid + i * 256;
            int sv = e >> 6, dv = e & 63;
            Vs[sv][dv] = v[(size_t)(b * TT + s0 + sv) * EE + h * 64 + dv];
        }
        __syncthreads();
#pragma unroll
        for (int s = 0; s < 16; s++) {
            float vv = Vs[s][d];
#pragma unroll
            for (int r = 0; r < 16; r++)
                acc[r] = fmaf(As[rg * 16 + r][s], vv, acc[r]);
        }
        __syncthreads();
    }
#pragma unroll
    for (int r = 0; r < 16; r++)
        o[(size_t)(b * TT + t0 + rg * 16 + r) * EE + h * 64 + d] = acc[r];
}

// ---------------------------------------------------------------------------
// Host launcher (graph-capturable: kernel launches only)
// ---------------------------------------------------------------------------
extern "C" void kernel_launch(void* const* d_in, const int* in_sizes, int n_in,
                              void* d_out, int out_size)
{
    const int*   idx     = (const int*)  d_in[0];
    const float* tok_emb = (const float*)d_in[1];
    const float* pos_emb = (const float*)d_in[2];
    const float* Wq      = (const float*)d_in[3];
    const float* Wk      = (const float*)d_in[4];
    const float* Wv      = (const float*)d_in[5];
    const float* Wo      = (const float*)d_in[6];
    const float* bo      = (const float*)d_in[7];
    const float* ln1_s   = (const float*)d_in[8];
    const float* ln1_b   = (const float*)d_in[9];
    const float* W1      = (const float*)d_in[10];
    const float* b1      = (const float*)d_in[11];
    const float* W2      = (const float*)d_in[12];
    const float* b2      = (const float*)d_in[13];
    const float* ln2_s   = (const float*)d_in[14];
    const float* ln2_b   = (const float*)d_in[15];
    const float* lnf_s   = (const float*)d_in[16];
    const float* lnf_b   = (const float*)d_in[17];
    const float* lm_w    = (const float*)d_in[18];
    const float* lm_b    = (const float*)d_in[19];
    float* out = (float*)d_out;

    float *x, *h, *q, *k, *v, *o, *ffn, *attn;
    cudaGetSymbolAddress((void**)&x,    g_x);
    cudaGetSymbolAddress((void**)&h,    g_h);
    cudaGetSymbolAddress((void**)&q,    g_q);
    cudaGetSymbolAddress((void**)&k,    g_k);
    cudaGetSymbolAddress((void**)&v,    g_v);
    cudaGetSymbolAddress((void**)&o,    g_o);
    cudaGetSymbolAddress((void**)&ffn,  g_ffn);
    cudaGetSymbolAddress((void**)&attn, g_attn);

    embed_kernel<<<(MM * EE) / 256, 256>>>(idx, tok_emb, pos_emb, x);

    dim3 gemm_E (EE  / 128, MM / 128);   // N=1024
    dim3 gemm_FF(FFF / 128, MM / 128);   // N=4096
    dim3 gemm_V (VV  / 128, MM / 128);   // N=32000

    for (int l = 0; l < LL; l++) {
        size_t wE  = (size_t)l * EE * EE;
        size_t wF1 = (size_t)l * EE * FFF;
        size_t wF2 = (size_t)l * FFF * EE;

        ln_kernel<<<MM, 256>>>(x, ln1_s + l * EE, ln1_b + l * EE, h);

        sgemm_kernel<false, false><<<gemm_E, 256>>>(h, Wq + wE, nullptr, nullptr, q, MM, EE, EE);
        sgemm_kernel<false, false><<<gemm_E, 256>>>(h, Wk + wE, nullptr, nullptr, k, MM, EE, EE);
        sgemm_kernel<false, false><<<gemm_E, 256>>>(h, Wv + wE, nullptr, nullptr, v, MM, EE, EE);

        scores_kernel<<<dim3(TT / 32, TT / 32, BB * NHH), 256>>>(q, k, attn);
        softmax_kernel<<<BB * NHH * TT, 128>>>(attn);
        pv_kernel<<<dim3(TT / 64, BB * NHH), 256>>>(attn, v, o);

        // x = x + o @ Wo + bo
        sgemm_kernel<true, false><<<gemm_E, 256>>>(o, Wo + wE, bo + l * EE, x, x, MM, EE, EE);

        ln_kernel<<<MM, 256>>>(x, ln2_s + l * EE, ln2_b + l * EE, h);

        // ffn = gelu(h @ W1 + b1)
        sgemm_kernel<false, true><<<gemm_FF, 256>>>(h, W1 + wF1, b1 + (size_t)l * FFF, nullptr, ffn, MM, FFF, EE);
        // x = x + ffn @ W2 + b2
        sgemm_kernel<true, false><<<gemm_E, 256>>>(ffn, W2 + wF2, b2 + l * EE, x, x, MM, EE, FFF);
    }

    ln_kernel<<<MM, 256>>>(x, lnf_s, lnf_b, h);
    sgemm_kernel<false, false><<<gemm_V, 256>>>(h, lm_w, lm_b, nullptr, out, MM, VV, EE);
}

// round 4
// speedup vs baseline: 1.9724x; 1.9724x over previous
#include <cuda_runtime.h>
#include <cuda_bf16.h>
#include <math.h>

// Problem constants
#define BB 2
#define TT 1024
#define LL 8
#define EE 1024
#define NHH 16
#define HDD 64
#define VV 32000
#define FFF 4096
#define MM (BB * TT)   // 2048 rows

#define WEL (LL * EE * EE)    // 8388608   per q/k/v/o weight set
#define WFL (LL * EE * FFF)   // 33554432  per W1 / W2 set
#define WVL (VV * EE)         // 32768000  lm head

typedef __nv_bfloat16 bf16;

// ---------------------------------------------------------------------------
// Device scratch (allocation-free: __device__ globals)
// ---------------------------------------------------------------------------
__device__ __align__(256) float g_x[MM * EE];
__device__ __align__(256) float g_q[MM * EE];
__device__ __align__(256) float g_k[MM * EE];
__device__ __align__(256) float g_v[MM * EE];
__device__ __align__(256) float g_attn[(size_t)BB * NHH * TT * TT];  // 134 MB

// Activation splits (written by LN / GELU / PV epilogues)
__device__ __align__(256) bf16 g_hhi[MM * EE];
__device__ __align__(256) bf16 g_hlo[MM * EE];
__device__ __align__(256) bf16 g_ohi[MM * EE];
__device__ __align__(256) bf16 g_olo[MM * EE];
__device__ __align__(256) bf16 g_fhi[MM * FFF];
__device__ __align__(256) bf16 g_flo[MM * FFF];

// Weight splits, TRANSPOSED to [N][K] per layer (B-side of GEMM)
__device__ __align__(256) bf16 g_wqt_hi[WEL];
__device__ __align__(256) bf16 g_wqt_lo[WEL];
__device__ __align__(256) bf16 g_wkt_hi[WEL];
__device__ __align__(256) bf16 g_wkt_lo[WEL];
__device__ __align__(256) bf16 g_wvt_hi[WEL];
__device__ __align__(256) bf16 g_wvt_lo[WEL];
__device__ __align__(256) bf16 g_wot_hi[WEL];
__device__ __align__(256) bf16 g_wot_lo[WEL];
__device__ __align__(256) bf16 g_w1t_hi[WFL];
__device__ __align__(256) bf16 g_w1t_lo[WFL];
__device__ __align__(256) bf16 g_w2t_hi[WFL];
__device__ __align__(256) bf16 g_w2t_lo[WFL];
__device__ __align__(256) bf16 g_lmt_hi[WVL];
__device__ __align__(256) bf16 g_lmt_lo[WVL];

// ---------------------------------------------------------------------------
// Helpers
// ---------------------------------------------------------------------------
__device__ __forceinline__ void cp_async16(void* smem, const void* gmem) {
    unsigned saddr = (unsigned)__cvta_generic_to_shared(smem);
    asm volatile("cp.async.cg.shared.global [%0], [%1], 16;\n" :: "r"(saddr), "l"(gmem));
}
__device__ __forceinline__ void cp_commit() { asm volatile("cp.async.commit_group;\n" ::); }
__device__ __forceinline__ void cp_wait0()  { asm volatile("cp.async.wait_group 0;\n" ::); }

__device__ __forceinline__ void mma_bf16(float* c, const unsigned* a, const unsigned* b) {
    asm volatile(
        "mma.sync.aligned.m16n8k16.row.col.f32.bf16.bf16.f32 "
        "{%0,%1,%2,%3}, {%4,%5,%6,%7}, {%8,%9}, {%0,%1,%2,%3};"
        : "+f"(c[0]), "+f"(c[1]), "+f"(c[2]), "+f"(c[3])
        : "r"(a[0]), "r"(a[1]), "r"(a[2]), "r"(a[3]), "r"(b[0]), "r"(b[1]));
}

__device__ __forceinline__ float gelu_exact(float c) {
    return 0.5f * c * (1.0f + erff(c * 0.70710678118654752f));
}

__device__ __forceinline__ void split_bf16(float v, bf16& hi, bf16& lo) {
    hi = __float2bfloat16(v);
    lo = __float2bfloat16(v - __bfloat162float(hi));
}

// ---------------------------------------------------------------------------
// Weight split + transpose: W [L][K][N] fp32 -> Wt_hi/lo [L][N][K] bf16
// ---------------------------------------------------------------------------
__global__ void split_t_kernel(const float* __restrict__ W,
                               bf16* __restrict__ th, bf16* __restrict__ tl,
                               int K, int N)
{
    size_t ls = (size_t)K * N;
    const float* Wl = W + blockIdx.z * ls;
    bf16* Hl = th + blockIdx.z * ls;
    bf16* Ll = tl + blockIdx.z * ls;

    __shared__ float tile[32][33];
    int k0 = blockIdx.y * 32, n0 = blockIdx.x * 32;
    int tx = threadIdx.x & 31, ty = threadIdx.x >> 5;   // 32 x 8

#pragma unroll
    for (int i = 0; i < 4; i++)
        tile[ty + 8 * i][tx] = Wl[(size_t)(k0 + ty + 8 * i) * N + n0 + tx];
    __syncthreads();
#pragma unroll
    for (int i = 0; i < 4; i++) {
        int n = ty + 8 * i;
        float v = tile[tx][n];            // = W[k0+tx][n0+n]
        bf16 hi, lo; split_bf16(v, hi, lo);
        size_t oidx = (size_t)(n0 + n) * K + k0 + tx;
        Hl[oidx] = hi;
        Ll[oidx] = lo;
    }
}

// ---------------------------------------------------------------------------
// Embedding
// ---------------------------------------------------------------------------
__global__ void embed_kernel(const int* __restrict__ idx,
                             const float* __restrict__ tok_emb,
                             const float* __restrict__ pos_emb,
                             float* __restrict__ x)
{
    int gid = blockIdx.x * blockDim.x + threadIdx.x;
    int bt = gid >> 10;
    int e  = gid & (EE - 1);
    int t  = bt & (TT - 1);
    int tok = idx[bt];
    x[gid] = tok_emb[(size_t)tok * EE + e] + pos_emb[t * EE + e];
}

// ---------------------------------------------------------------------------
// LayerNorm -> bf16 hi/lo split output
// ---------------------------------------------------------------------------
__global__ void ln_split_kernel(const float* __restrict__ x,
                                const float* __restrict__ scale,
                                const float* __restrict__ bias,
                                bf16* __restrict__ ohi, bf16* __restrict__ olo)
{
    int row = blockIdx.x;
    int tid = threadIdx.x;
    const float* xr = x + (size_t)row * EE;
    float v[4];
#pragma unroll
    for (int i = 0; i < 4; i++) v[i] = xr[tid + i * 256];

    __shared__ float red[256];
    red[tid] = v[0] + v[1] + v[2] + v[3];
    __syncthreads();
    for (int off = 128; off > 0; off >>= 1) {
        if (tid < off) red[tid] += red[tid + off];
        __syncthreads();
    }
    float mean = red[0] * (1.0f / EE);
    __syncthreads();

    float sq = 0.f;
#pragma unroll
    for (int i = 0; i < 4; i++) { float d = v[i] - mean; sq += d * d; }
    red[tid] = sq;
    __syncthreads();
    for (int off = 128; off > 0; off >>= 1) {
        if (tid < off) red[tid] += red[tid + off];
        __syncthreads();
    }
    float rstd = rsqrtf(red[0] * (1.0f / EE) + 1e-5f);

#pragma unroll
    for (int i = 0; i < 4; i++) {
        int col = tid + i * 256;
        float y = (v[i] - mean) * rstd * scale[col] + bias[col];
        bf16 hi, lo; split_bf16(y, hi, lo);
        ohi[(size_t)row * EE + col] = hi;
        olo[(size_t)row * EE + col] = lo;
    }
}

// ---------------------------------------------------------------------------
// Tensor-core GEMM with 3-term bf16 split operands.
// C[M,N] = A[M,K] @ B[K,N] where A = Ahi+Alo (row-major [M][K]),
// B given transposed as [N][K] hi/lo.
// BM=BN=128, BK=32, 256 threads (8 warps, 2x4), warp tile 64x32,
// m16n8k16 mma, double-buffered cp.async. Dynamic smem 80KB.
// MODE: 0 = (+bias if non-null) -> fp32 C
//       1 = +bias +res          -> fp32 C (res may alias C)
//       2 = gelu(acc+bias)      -> bf16 hi/lo split outputs
// ---------------------------------------------------------------------------
#define SA 40           // padded k-stride in bf16 elems (conflict-free)
#define SMEM_ELEMS_BUF (4 * 128 * SA)    // 4 arrays per buffer
#define SGEMM_SMEM (2 * SMEM_ELEMS_BUF * 2)  // bytes = 81920

template <int MODE>
__global__ __launch_bounds__(256)
void sgemm_ts(const bf16* __restrict__ Ahi, const bf16* __restrict__ Alo,
              const bf16* __restrict__ Bhi, const bf16* __restrict__ Blo,
              const float* __restrict__ bias, const float* res,
              float* C, bf16* Chi, bf16* Clo, int N, int K)
{
    extern __shared__ __align__(16) char dsm[];
    bf16* S = (bf16*)dsm;

    int tid  = threadIdx.x;
    int bm   = blockIdx.y * 128;
    int bn   = blockIdx.x * 128;
    int wid  = tid >> 5, lane = tid & 31;
    int wm   = wid >> 2, wn = wid & 3;         // 2 x 4 warp grid
    int g    = lane >> 2, t4 = lane & 3;

    float acc[4][4][4];
#pragma unroll
    for (int a = 0; a < 4; a++)
#pragma unroll
        for (int b = 0; b < 4; b++)
#pragma unroll
            for (int c = 0; c < 4; c++) acc[a][b][c] = 0.f;

    int ntiles = K / 32;

    // per-buffer array bases (elements)
    //   ahi: +0, alo: +5120, bhi: +10240, blo: +15360
#define ISSUE(buf, k0)                                                            \
    {                                                                             \
        bf16* ah = S + (buf) * SMEM_ELEMS_BUF;                                    \
        bf16* al = ah + 128 * SA;                                                 \
        bf16* bh = al + 128 * SA;                                                 \
        bf16* bl = bh + 128 * SA;                                                 \
        _Pragma("unroll")                                                         \
        for (int cc = 0; cc < 2; cc++) {                                          \
            int c = tid + cc * 256;                                               \
            int r = c >> 2, q8 = (c & 3) * 8;                                     \
            size_t asrc = (size_t)(bm + r) * K + (k0) + q8;                       \
            size_t bsrc = (size_t)(bn + r) * K + (k0) + q8;                       \
            cp_async16(ah + r * SA + q8, Ahi + asrc);                             \
            cp_async16(al + r * SA + q8, Alo + asrc);                             \
            cp_async16(bh + r * SA + q8, Bhi + bsrc);                             \
            cp_async16(bl + r * SA + q8, Blo + bsrc);                             \
        }                                                                         \
        cp_commit();                                                              \
    }

    ISSUE(0, 0);

    int buf = 0;
    for (int t = 0; t < ntiles; t++) {
        cp_wait0();
        __syncthreads();

        if (t + 1 < ntiles) ISSUE(buf ^ 1, (t + 1) * 32);

        const bf16* ah = S + buf * SMEM_ELEMS_BUF;
        const bf16* al = ah + 128 * SA;
        const bf16* bh = al + 128 * SA;
        const bf16* bl = bh + 128 * SA;

#pragma unroll
        for (int ks = 0; ks < 32; ks += 16) {
            unsigned Ah[4][4], Al[4][4], Bh[4][2], Bl[4][2];
#pragma unroll
            for (int mt = 0; mt < 4; mt++) {
                int r0 = (wm * 64 + mt * 16 + g) * SA + ks + 2 * t4;
                Ah[mt][0] = *(const unsigned*)(ah + r0);
                Ah[mt][1] = *(const unsigned*)(ah + r0 + 8 * SA);
                Ah[mt][2] = *(const unsigned*)(ah + r0 + 8);
                Ah[mt][3] = *(const unsigned*)(ah + r0 + 8 * SA + 8);
                Al[mt][0] = *(const unsigned*)(al + r0);
                Al[mt][1] = *(const unsigned*)(al + r0 + 8 * SA);
                Al[mt][2] = *(const unsigned*)(al + r0 + 8);
                Al[mt][3] = *(const unsigned*)(al + r0 + 8 * SA + 8);
            }
#pragma unroll
            for (int nt = 0; nt < 4; nt++) {
                int b0 = (wn * 32 + nt * 8 + g) * SA + ks + 2 * t4;
                Bh[nt][0] = *(const unsigned*)(bh + b0);
                Bh[nt][1] = *(const unsigned*)(bh + b0 + 8);
                Bl[nt][0] = *(const unsigned*)(bl + b0);
                Bl[nt][1] = *(const unsigned*)(bl + b0 + 8);
            }
#pragma unroll
            for (int mt = 0; mt < 4; mt++)
#pragma unroll
                for (int nt = 0; nt < 4; nt++) {
                    mma_bf16(acc[mt][nt], Ah[mt], Bh[nt]);
                    mma_bf16(acc[mt][nt], Ah[mt], Bl[nt]);
                    mma_bf16(acc[mt][nt], Al[mt], Bh[nt]);
                }
        }
        __syncthreads();
        buf ^= 1;
    }
#undef ISSUE

    // Epilogue. c0,c1 -> (row, col..col+1); c2,c3 -> (row+8, ...)
#pragma unroll
    for (int mt = 0; mt < 4; mt++)
#pragma unroll
        for (int nt = 0; nt < 4; nt++) {
            int row = bm + wm * 64 + mt * 16 + g;
            int col = bn + wn * 32 + nt * 8 + 2 * t4;
            float v0 = acc[mt][nt][0], v1 = acc[mt][nt][1];
            float v2 = acc[mt][nt][2], v3 = acc[mt][nt][3];
            if (MODE == 0) {
                if (bias) {
                    float b0 = bias[col], b1 = bias[col + 1];
                    v0 += b0; v1 += b1; v2 += b0; v3 += b1;
                }
                *(float2*)&C[(size_t)row * N + col]       = make_float2(v0, v1);
                *(float2*)&C[(size_t)(row + 8) * N + col] = make_float2(v2, v3);
            } else if (MODE == 1) {
                float b0 = bias[col], b1 = bias[col + 1];
                v0 += b0 + res[(size_t)row * N + col];
                v1 += b1 + res[(size_t)row * N + col + 1];
                v2 += b0 + res[(size_t)(row + 8) * N + col];
                v3 += b1 + res[(size_t)(row + 8) * N + col + 1];
                *(float2*)&C[(size_t)row * N + col]       = make_float2(v0, v1);
                *(float2*)&C[(size_t)(row + 8) * N + col] = make_float2(v2, v3);
            } else {
                float b0 = bias[col], b1 = bias[col + 1];
                v0 = gelu_exact(v0 + b0); v1 = gelu_exact(v1 + b1);
                v2 = gelu_exact(v2 + b0); v3 = gelu_exact(v3 + b1);
                bf16 h0, l0, h1, l1;
                __nv_bfloat162 ph, pl;
                split_bf16(v0, h0, l0); split_bf16(v1, h1, l1);
                ph.x = h0; ph.y = h1; pl.x = l0; pl.y = l1;
                *(__nv_bfloat162*)&Chi[(size_t)row * N + col] = ph;
                *(__nv_bfloat162*)&Clo[(size_t)row * N + col] = pl;
                split_bf16(v2, h0, l0); split_bf16(v3, h1, l1);
                ph.x = h0; ph.y = h1; pl.x = l0; pl.y = l1;
                *(__nv_bfloat162*)&Chi[(size_t)(row + 8) * N + col] = ph;
                *(__nv_bfloat162*)&Clo[(size_t)(row + 8) * N + col] = pl;
            }
        }
}

// ---------------------------------------------------------------------------
// Attention scores (fp32 SIMT, causal tile skip)
// ---------------------------------------------------------------------------
__global__ void scores_kernel(const float* __restrict__ q,
                              const float* __restrict__ k,
                              float* __restrict__ attn)
{
    int bh = blockIdx.z;
    int b = bh >> 4, h = bh & 15;
    int t0 = blockIdx.y * 32, s0 = blockIdx.x * 32;
    if (s0 > t0 + 31) return;

    __shared__ float Qs[32][64];
    __shared__ float Ks[32][65];
    int tid = threadIdx.x;
#pragma unroll
    for (int i = 0; i < 8; i++) {
        int e = tid + i * 256;
        int r = e >> 6, d = e & 63;
        Qs[r][d] = q[(size_t)(b * TT + t0 + r) * EE + h * 64 + d];
        Ks[r][d] = k[(size_t)(b * TT + s0 + r) * EE + h * 64 + d];
    }
    __syncthreads();

    int tx = tid & 31, ty = tid >> 5;
    float acc[4] = {0.f, 0.f, 0.f, 0.f};
#pragma unroll 16
    for (int d = 0; d < 64; d++) {
        float kv = Ks[tx][d];
        acc[0] = fmaf(Qs[ty][d],      kv, acc[0]);
        acc[1] = fmaf(Qs[ty +  8][d], kv, acc[1]);
        acc[2] = fmaf(Qs[ty + 16][d], kv, acc[2]);
        acc[3] = fmaf(Qs[ty + 24][d], kv, acc[3]);
    }
#pragma unroll
    for (int i = 0; i < 4; i++) {
        int t = t0 + ty + 8 * i;
        attn[((size_t)bh * TT + t) * TT + s0 + tx] = acc[i] * 0.125f;
    }
}

__global__ void softmax_kernel(float* __restrict__ attn)
{
    int r = blockIdx.x;
    int t = r & (TT - 1);
    float* row = attn + (size_t)r * TT;
    int n = t + 1;
    int tid = threadIdx.x;
    __shared__ float red[128];

    float m = -1e30f;
    for (int i = tid; i < n; i += 128) m = fmaxf(m, row[i]);
    red[tid] = m;
    __syncthreads();
    for (int off = 64; off > 0; off >>= 1) {
        if (tid < off) red[tid] = fmaxf(red[tid], red[tid + off]);
        __syncthreads();
    }
    m = red[0];
    __syncthreads();

    float s = 0.f;
    for (int i = tid; i < n; i += 128) s += __expf(row[i] - m);
    red[tid] = s;
    __syncthreads();
    for (int off = 64; off > 0; off >>= 1) {
        if (tid < off) red[tid] += red[tid + off];
        __syncthreads();
    }
    float inv = 1.0f / red[0];

    for (int i = tid; i < TT; i += 128)
        row[i] = (i < n) ? __expf(row[i] - m) * inv : 0.f;
}

// ---------------------------------------------------------------------------
// PV -> bf16 hi/lo split output
// ---------------------------------------------------------------------------
__global__ void pv_kernel(const float* __restrict__ attn,
                          const float* __restrict__ v,
                          bf16* __restrict__ ohi, bf16* __restrict__ olo)
{
    int bh = blockIdx.y;
    int b = bh >> 4, h = bh & 15;
    int t0 = blockIdx.x * 64;
    int tid = threadIdx.x;
    int d = tid & 63, rg = tid >> 6;

    __shared__ float As[64][17];
    __shared__ float Vs[16][64];
    float acc[16];
#pragma unroll
    for (int r = 0; r < 16; r++) acc[r] = 0.f;

    for (int s0 = 0; s0 < TT; s0 += 16) {
        if (s0 > t0 + 63) break;
#pragma unroll
        for (int i = 0; i < 4; i++) {
            int e = tid + i * 256;
            int r = e >> 4, c = e & 15;
            As[r][c] = attn[((size_t)bh * TT + t0 + r) * TT + s0 + c];
        }
#pragma unroll
        for (int i = 0; i < 4; i++) {
            int e = tid + i * 256;
            int sv = e >> 6, dv = e & 63;
            Vs[sv][dv] = v[(size_t)(b * TT + s0 + sv) * EE + h * 64 + dv];
        }
        __syncthreads();
#pragma unroll
        for (int s = 0; s < 16; s++) {
            float vv = Vs[s][d];
#pragma unroll
            for (int r = 0; r < 16; r++)
                acc[r] = fmaf(As[rg * 16 + r][s], vv, acc[r]);
        }
        __syncthreads();
    }
#pragma unroll
    for (int r = 0; r < 16; r++) {
        bf16 hi, lo; split_bf16(acc[r], hi, lo);
        size_t oidx = (size_t)(b * TT + t0 + rg * 16 + r) * EE + h * 64 + d;
        ohi[oidx] = hi;
        olo[oidx] = lo;
    }
}

// ---------------------------------------------------------------------------
// Host launcher (graph-capturable)
// ---------------------------------------------------------------------------
extern "C" void kernel_launch(void* const* d_in, const int* in_sizes, int n_in,
                              void* d_out, int out_size)
{
    const int*   idx     = (const int*)  d_in[0];
    const float* tok_emb = (const float*)d_in[1];
    const float* pos_emb = (const float*)d_in[2];
    const float* Wq      = (const float*)d_in[3];
    const float* Wk      = (const float*)d_in[4];
    const float* Wv      = (const float*)d_in[5];
    const float* Wo      = (const float*)d_in[6];
    const float* bo      = (const float*)d_in[7];
    const float* ln1_s   = (const float*)d_in[8];
    const float* ln1_b   = (const float*)d_in[9];
    const float* W1      = (const float*)d_in[10];
    const float* b1      = (const float*)d_in[11];
    const float* W2      = (const float*)d_in[12];
    const float* b2      = (const float*)d_in[13];
    const float* ln2_s   = (const float*)d_in[14];
    const float* ln2_b   = (const float*)d_in[15];
    const float* lnf_s   = (const float*)d_in[16];
    const float* lnf_b   = (const float*)d_in[17];
    const float* lm_w    = (const float*)d_in[18];
    const float* lm_b    = (const float*)d_in[19];
    float* out = (float*)d_out;

    float *x, *q, *k, *v, *attn;
    bf16 *hhi, *hlo, *ohi, *olo, *fhi, *flo;
    bf16 *wqh, *wql, *wkh, *wkl, *wvh, *wvl, *woh, *wol;
    bf16 *w1h, *w1l, *w2h, *w2l, *lmh, *lml;
    cudaGetSymbolAddress((void**)&x,    g_x);
    cudaGetSymbolAddress((void**)&q,    g_q);
    cudaGetSymbolAddress((void**)&k,    g_k);
    cudaGetSymbolAddress((void**)&v,    g_v);
    cudaGetSymbolAddress((void**)&attn, g_attn);
    cudaGetSymbolAddress((void**)&hhi,  g_hhi);
    cudaGetSymbolAddress((void**)&hlo,  g_hlo);
    cudaGetSymbolAddress((void**)&ohi,  g_ohi);
    cudaGetSymbolAddress((void**)&olo,  g_olo);
    cudaGetSymbolAddress((void**)&fhi,  g_fhi);
    cudaGetSymbolAddress((void**)&flo,  g_flo);
    cudaGetSymbolAddress((void**)&wqh,  g_wqt_hi);
    cudaGetSymbolAddress((void**)&wql,  g_wqt_lo);
    cudaGetSymbolAddress((void**)&wkh,  g_wkt_hi);
    cudaGetSymbolAddress((void**)&wkl,  g_wkt_lo);
    cudaGetSymbolAddress((void**)&wvh,  g_wvt_hi);
    cudaGetSymbolAddress((void**)&wvl,  g_wvt_lo);
    cudaGetSymbolAddress((void**)&woh,  g_wot_hi);
    cudaGetSymbolAddress((void**)&wol,  g_wot_lo);
    cudaGetSymbolAddress((void**)&w1h,  g_w1t_hi);
    cudaGetSymbolAddress((void**)&w1l,  g_w1t_lo);
    cudaGetSymbolAddress((void**)&w2h,  g_w2t_hi);
    cudaGetSymbolAddress((void**)&w2l,  g_w2t_lo);
    cudaGetSymbolAddress((void**)&lmh,  g_lmt_hi);
    cudaGetSymbolAddress((void**)&lml,  g_lmt_lo);

    cudaFuncSetAttribute(sgemm_ts<0>, cudaFuncAttributeMaxDynamicSharedMemorySize, SGEMM_SMEM);
    cudaFuncSetAttribute(sgemm_ts<1>, cudaFuncAttributeMaxDynamicSharedMemorySize, SGEMM_SMEM);
    cudaFuncSetAttribute(sgemm_ts<2>, cudaFuncAttributeMaxDynamicSharedMemorySize, SGEMM_SMEM);

    // Weight split+transpose (per replay; ~200us of bandwidth)
    split_t_kernel<<<dim3(EE / 32, EE / 32, LL), 256>>>(Wq, wqh, wql, EE, EE);
    split_t_kernel<<<dim3(EE / 32, EE / 32, LL), 256>>>(Wk, wkh, wkl, EE, EE);
    split_t_kernel<<<dim3(EE / 32, EE / 32, LL), 256>>>(Wv, wvh, wvl, EE, EE);
    split_t_kernel<<<dim3(EE / 32, EE / 32, LL), 256>>>(Wo, woh, wol, EE, EE);
    split_t_kernel<<<dim3(FFF / 32, EE / 32, LL), 256>>>(W1, w1h, w1l, EE, FFF);
    split_t_kernel<<<dim3(EE / 32, FFF / 32, LL), 256>>>(W2, w2h, w2l, FFF, EE);
    split_t_kernel<<<dim3(VV / 32, EE / 32, 1), 256>>>(lm_w, lmh, lml, EE, VV);

    embed_kernel<<<(MM * EE) / 256, 256>>>(idx, tok_emb, pos_emb, x);

    dim3 gE (EE  / 128, MM / 128);
    dim3 gFF(FFF / 128, MM / 128);
    dim3 gV (VV  / 128, MM / 128);

    for (int l = 0; l < LL; l++) {
        size_t wE  = (size_t)l * EE * EE;
        size_t wF  = (size_t)l * EE * FFF;

        ln_split_kernel<<<MM, 256>>>(x, ln1_s + l * EE, ln1_b + l * EE, hhi, hlo);

        sgemm_ts<0><<<gE, 256, SGEMM_SMEM>>>(hhi, hlo, wqh + wE, wql + wE,
                                             nullptr, nullptr, q, nullptr, nullptr, EE, EE);
        sgemm_ts<0><<<gE, 256, SGEMM_SMEM>>>(hhi, hlo, wkh + wE, wkl + wE,
                                             nullptr, nullptr, k, nullptr, nullptr, EE, EE);
        sgemm_ts<0><<<gE, 256, SGEMM_SMEM>>>(hhi, hlo, wvh + wE, wvl + wE,
                                             nullptr, nullptr, v, nullptr, nullptr, EE, EE);

        scores_kernel<<<dim3(TT / 32, TT / 32, BB * NHH), 256>>>(q, k, attn);
        softmax_kernel<<<BB * NHH * TT, 128>>>(attn);
        pv_kernel<<<dim3(TT / 64, BB * NHH), 256>>>(attn, v, ohi, olo);

        // x = x + o @ Wo + bo
        sgemm_ts<1><<<gE, 256, SGEMM_SMEM>>>(ohi, olo, woh + wE, wol + wE,
                                             bo + l * EE, x, x, nullptr, nullptr, EE, EE);

        ln_split_kernel<<<MM, 256>>>(x, ln2_s + l * EE, ln2_b + l * EE, hhi, hlo);

        // ffn = gelu(h @ W1 + b1) -> split
        sgemm_ts<2><<<gFF, 256, SGEMM_SMEM>>>(hhi, hlo, w1h + wF, w1l + wF,
                                              b1 + (size_t)l * FFF, nullptr,
                                              nullptr, fhi, flo, FFF, EE);
        // x = x + ffn @ W2 + b2
        sgemm_ts<1><<<gE, 256, SGEMM_SMEM>>>(fhi, flo, w2h + wF, w2l + wF,
                                             b2 + l * EE, x, x, nullptr, nullptr, EE, FFF);
    }

    ln_split_kernel<<<MM, 256>>>(x, lnf_s, lnf_b, hhi, hlo);
    sgemm_ts<0><<<gV, 256, SGEMM_SMEM>>>(hhi, hlo, lmh, lml,
                                         lm_b, nullptr, out, nullptr, nullptr, VV, EE);
}